// round 7
// baseline (speedup 1.0000x reference)
#include <cuda_runtime.h>

// DifferentiableBezierRenderer — fully fused single-kernel version.
//
// wind[y][gx] = sum_e c_e(y) * sigmoid(xc_e(y) - gx)
// where c, xc depend only on (edge,row), and sigmoid saturates outside a
// 41-column band around xc:  step part -> per-row difference array + scan,
// band part -> <=41 exact sigmoids per active (edge,row).
//
// One block per row (512 blocks x 512 threads). Everything lives in smem:
//   scp : staged control points (386 floats)
//   spx/spy : 2048 bezier samples (computed cooperatively per block;
//             warp-aligned so control-point LDS reads are broadcasts)
//   sD  : difference array (scanned at the end)
//   sB  : exact transition-band accumulator
// No global scratch, no global atomics, no inter-kernel traffic, 1 launch.

#define HH 512
#define WW 512
#define MM 2048           // 64 segments * 32 samples
#define T_BAND 20.0f      // sigmoid saturation cutoff (e^-20 ~ 2e-9)

__device__ __forceinline__ float sigm(float z) {
    return 1.0f / (1.0f + __expf(-z));
}

__global__ void __launch_bounds__(512)
k_render(const float* __restrict__ cp,
         const float* __restrict__ color,
         float* __restrict__ out)
{
    __shared__ float scp[386];      // control points (193 x 2, interleaved)
    __shared__ float spx[MM];
    __shared__ float spy[MM];
    __shared__ float sD[WW];        // difference array
    __shared__ float sB[WW];        // exact band accumulator
    __shared__ float wsum[16];

    const int tid = threadIdx.x;
    const int y   = blockIdx.x;

    if (tid < 386) scp[tid] = cp[tid];
    sD[tid] = 0.0f;
    sB[tid] = 0.0f;
    __syncthreads();

    // ---- cooperative bezier sampling (4 points per thread) ----
    // idx consecutive across lanes -> whole warp shares one segment s,
    // so scp reads are smem broadcasts (free).
    #pragma unroll
    for (int k = 0; k < 4; ++k) {
        int idx = tid + k * 512;
        int s = idx >> 5;            // segment 0..63
        int i = idx & 31;            // sample 0..31
        float t  = (float)i / 31.0f; // linspace(0,1,32)
        float mt = 1.0f - t;
        float w0 = mt * mt * mt;
        float w1 = 3.0f * mt * mt * t;
        float w2 = 3.0f * mt * t * t;
        float w3 = t * t * t;
        const float* c0 = scp + 6 * s;
        spx[idx] = w0 * c0[0] + w1 * c0[2] + w2 * c0[4] + w3 * c0[6];
        spy[idx] = w0 * c0[1] + w1 * c0[3] + w2 * c0[5] + w3 * c0[7];
    }
    __syncthreads();

    // ---- edge loop: 4 edges per thread, this block's row only ----
    const float fy = (float)y;
    #pragma unroll
    for (int k = 0; k < 4; ++k) {
        int e  = tid + k * 512;
        int e1 = (e + 1) & (MM - 1);

        float y0 = spy[e], y1 = spy[e1];
        float dy = y1 - y0;
        if (fabsf(dy) < 1e-6f) continue;            // reference mask

        float t = (fy - y0) / (dy + 1e-8f);         // reference formula
        if (t < -1.2f || t > 2.2f) continue;        // c would be < ~4e-11

        float c = sigm(20.0f * t) * sigm(20.0f * (1.0f - t));  // valid_t
        if (c < 1e-9f) continue;
        if (dy < 0.0f) c = -c;                      // * sign(dy)

        float x0 = spx[e], x1 = spx[e1];
        float xc = x0 + t * (x1 - x0);

        int gL = (int)ceilf(xc - T_BAND);
        int gR = (int)floorf(xc + T_BAND);

        // Step part: contribution c for gx in [0, jl)
        int jl = gL < 0 ? 0 : (gL > WW ? WW : gL);
        if (jl > 0) {
            atomicAdd(&sD[0], c);
            if (jl < WW) atomicAdd(&sD[jl], -c);
        }

        // Exact band: c * sigmoid(xc - gx), gx in [gL, gR] ∩ [0, W)
        int b0 = gL < 0 ? 0 : gL;
        int b1 = gR > WW - 1 ? WW - 1 : gR;
        for (int gx = b0; gx <= b1; ++gx)
            atomicAdd(&sB[gx], c * sigm(xc - (float)gx));
    }
    __syncthreads();

    // ---- inclusive scan of sD + band, sigmoid, RGBA store ----
    int lane = tid & 31;
    int wid  = tid >> 5;

    float v = sD[tid];
    #pragma unroll
    for (int o = 1; o < 32; o <<= 1) {
        float n = __shfl_up_sync(0xffffffffu, v, o);
        if (lane >= o) v += n;
    }
    if (lane == 31) wsum[wid] = v;
    __syncthreads();

    if (wid == 0) {
        float w = (lane < 16) ? wsum[lane] : 0.0f;
        #pragma unroll
        for (int o = 1; o < 16; o <<= 1) {
            float n = __shfl_up_sync(0xffffffffu, w, o);
            if (lane >= o) w += n;
        }
        if (lane < 16) wsum[lane] = w;
    }
    __syncthreads();

    float prefix = (wid > 0) ? wsum[wid - 1] : 0.0f;
    float wind   = v + prefix + sB[tid];
    float alpha  = 1.0f / (1.0f + __expf(-4.0f * wind));

    float4 px = make_float4(color[0], color[1], color[2], alpha);
    reinterpret_cast<float4*>(out)[y * WW + tid] = px;
}

// ---------------------------------------------------------------------------
extern "C" void kernel_launch(void* const* d_in, const int* in_sizes, int n_in,
                              void* d_out, int out_size) {
    const float* cp    = (const float*)d_in[0];   // (193,2) f32
    const float* color = (const float*)d_in[1];   // (3,)   f32
    float* out = (float*)d_out;                   // (512,512,4) f32

    k_render<<<HH, 512>>>(cp, color, out);
}

// round 12
// speedup vs baseline: 3.7858x; 3.7858x over previous
#include <cuda_runtime.h>

// DifferentiableBezierRenderer — fused single kernel, bucketed-gather band.
//
// wind[y][gx] = sum_e c_e(y) * sigmoid(xc_e(y) - gx)
//   c, xc depend only on (edge,row). sigmoid saturates outside |z| > T:
//   - step part (gx < xc - T, contributes exactly c): per-row difference
//     array + block scan (same-address adds warp-reduced first).
//   - band part (<=32 columns with T=15.5): active edges bucketed by the
//     16 warp-owned 32-column windows; each warp gathers ONLY its bucket,
//     accumulating into registers. No atomics on the band at all.
//
// One block per row (512 x 512). Bezier points computed cooperatively per
// block in smem (warp-aligned -> control-point LDS reads are broadcasts).

#define HH 512
#define WW 512
#define MM 2048           // 64 segments * 32 samples
#define TB 15.5f          // band half-width; tail err ~e^-15.5 ~ 1.8e-7

__device__ __forceinline__ float sigm(float z) {
    return 1.0f / (1.0f + __expf(-z));
}

__global__ void __launch_bounds__(512)
k_render(const float* __restrict__ cp,
         const float* __restrict__ color,
         float* __restrict__ out)
{
    __shared__ float  scp[386];     // control points (193 x 2 interleaved)
    __shared__ float  spx[MM];
    __shared__ float  spy[MM];
    __shared__ float  sD[WW];       // step difference array
    __shared__ float2 flat[2 * MM]; // bucketed (c, xc); <=2 buckets/edge
    __shared__ int    bcount[16];
    __shared__ int    boff[16];
    __shared__ int    bfill[16];
    __shared__ float  wsum[16];

    const int tid  = threadIdx.x;
    const int y    = blockIdx.x;
    const int lane = tid & 31;
    const int wid  = tid >> 5;

    if (tid < 386) scp[tid] = cp[tid];
    sD[tid] = 0.0f;
    if (tid < 16) { bcount[tid] = 0; bfill[tid] = 0; }
    __syncthreads();

    // ---- cooperative bezier sampling (4 pts/thread, warp shares segment) ----
    #pragma unroll
    for (int k = 0; k < 4; ++k) {
        int idx = tid + k * 512;
        int s = idx >> 5;            // segment 0..63
        int i = idx & 31;            // sample 0..31
        float t  = (float)i * (1.0f / 31.0f);   // linspace(0,1,32)
        float mt = 1.0f - t;
        float w0 = mt * mt * mt;
        float w1 = 3.0f * mt * mt * t;
        float w2 = 3.0f * mt * t * t;
        float w3 = t * t * t;
        const float* c0 = scp + 6 * s;
        spx[idx] = w0 * c0[0] + w1 * c0[2] + w2 * c0[4] + w3 * c0[6];
        spy[idx] = w0 * c0[1] + w1 * c0[3] + w2 * c0[5] + w3 * c0[7];
    }
    __syncthreads();

    const float fy = (float)y;

    // ---- pass A: test edges, scatter step part, count bucket entries ----
    #pragma unroll
    for (int k = 0; k < 4; ++k) {
        int e  = tid + k * 512;
        int e1 = (e + 1) & (MM - 1);
        float y0 = spy[e], y1 = spy[e1];
        float dy = y1 - y0;
        bool ok = fabsf(dy) >= 1e-6f;               // reference mask
        float t = (fy - y0) / (dy + 1e-8f);         // reference formula
        ok = ok && (t >= -1.2f) && (t <= 2.2f);     // c would be < 4e-11
        float c = 0.0f, gl = 0.0f;
        bool band = false;
        if (ok) {
            c  = sigm(20.0f * t) * sigm(20.0f * (1.0f - t));  // valid_t
            ok = c >= 1e-9f;
            if (dy < 0.0f) c = -c;                  // * sign(dy)
            float xc = spx[e] + t * (spx[e1] - spx[e]);
            gl = ceilf(xc - TB);                    // first band column
            ok   = ok && (gl + 31.0f >= 0.0f);      // not fully off-left
            band = ok && (gl < 512.0f);             // band reaches screen
        }
        // step: contribution c for columns [0, gl). sD[0] adds are
        // warp-reduced (same-address ATOMS would serialize).
        float cstep = (ok && gl > 0.0f) ? c : 0.0f;
        #pragma unroll
        for (int o = 16; o > 0; o >>= 1)
            cstep += __shfl_xor_sync(0xffffffffu, cstep, o);
        if (lane == 0 && cstep != 0.0f) atomicAdd(&sD[0], cstep);
        if (ok && gl > 0.0f && gl < 512.0f) atomicAdd(&sD[(int)gl], -c);

        if (band) {
            int igl = (int)gl;
            int b0 = igl >> 5;        if (b0 < 0)  b0 = 0;
            int b1 = (igl + 31) >> 5; if (b1 > 15) b1 = 15;
            atomicAdd(&bcount[b0], 1);
            if (b1 != b0) atomicAdd(&bcount[b1], 1);
        }
    }
    __syncthreads();

    // ---- exclusive prefix over the 16 bucket counts ----
    if (wid == 0) {
        int v = (lane < 16) ? bcount[lane] : 0;
        int s = v;
        #pragma unroll
        for (int o = 1; o < 16; o <<= 1) {
            int n = __shfl_up_sync(0xffffffffu, s, o);
            if (lane >= o) s += n;
        }
        if (lane < 16) boff[lane] = s - v;
    }
    __syncthreads();

    // ---- pass B: recompute actives (cheaper than holding regs), fill ----
    #pragma unroll
    for (int k = 0; k < 4; ++k) {
        int e  = tid + k * 512;
        int e1 = (e + 1) & (MM - 1);
        float y0 = spy[e], y1 = spy[e1];
        float dy = y1 - y0;
        if (fabsf(dy) < 1e-6f) continue;
        float t = (fy - y0) / (dy + 1e-8f);
        if (t < -1.2f || t > 2.2f) continue;
        float c = sigm(20.0f * t) * sigm(20.0f * (1.0f - t));
        if (c < 1e-9f) continue;
        if (dy < 0.0f) c = -c;
        float xc = spx[e] + t * (spx[e1] - spx[e]);
        float gl = ceilf(xc - TB);
        if (gl + 31.0f < 0.0f || gl >= 512.0f) continue;
        int igl = (int)gl;
        int b0 = igl >> 5;        if (b0 < 0)  b0 = 0;
        int b1 = (igl + 31) >> 5; if (b1 > 15) b1 = 15;
        int p = atomicAdd(&bfill[b0], 1);
        flat[boff[b0] + p] = make_float2(c, xc);
        if (b1 != b0) {
            p = atomicAdd(&bfill[b1], 1);
            flat[boff[b1] + p] = make_float2(c, xc);
        }
    }
    __syncthreads();

    // ---- band gather: warp w owns columns [32w, 32w+31]; registers only ----
    float acc = 0.0f;
    const float fgx = (float)tid;
    {
        const int n    = bcount[wid];
        const int base = boff[wid];
        for (int i = 0; i < n; ++i) {
            float2 p  = flat[base + i];      // LDS.64 broadcast
            float gl  = ceilf(p.y - TB);
            float rel = fgx - gl;
            if (rel >= 0.0f && rel < 32.0f)
                acc += p.x * sigm(p.y - fgx);
        }
    }

    // ---- inclusive scan of sD, combine, sigmoid, RGBA store ----
    float v = sD[tid];
    #pragma unroll
    for (int o = 1; o < 32; o <<= 1) {
        float n = __shfl_up_sync(0xffffffffu, v, o);
        if (lane >= o) v += n;
    }
    if (lane == 31) wsum[wid] = v;
    __syncthreads();
    if (wid == 0) {
        float w = (lane < 16) ? wsum[lane] : 0.0f;
        #pragma unroll
        for (int o = 1; o < 16; o <<= 1) {
            float n = __shfl_up_sync(0xffffffffu, w, o);
            if (lane >= o) w += n;
        }
        if (lane < 16) wsum[lane] = w;
    }
    __syncthreads();

    float prefix = (wid > 0) ? wsum[wid - 1] : 0.0f;
    float wind   = v + prefix + acc;
    float alpha  = 1.0f / (1.0f + __expf(-4.0f * wind));

    float4 px = make_float4(color[0], color[1], color[2], alpha);
    reinterpret_cast<float4*>(out)[y * WW + tid] = px;
}

// ---------------------------------------------------------------------------
extern "C" void kernel_launch(void* const* d_in, const int* in_sizes, int n_in,
                              void* d_out, int out_size) {
    const float* cp    = (const float*)d_in[0];   // (193,2) f32
    const float* color = (const float*)d_in[1];   // (3,)   f32
    float* out = (float*)d_out;                   // (512,512,4) f32

    k_render<<<HH, 512>>>(cp, color, out);
}

// round 16
// speedup vs baseline: 4.5925x; 1.2131x over previous
#include <cuda_runtime.h>

// DifferentiableBezierRenderer — fused single kernel, v3.
//
// wind[y][gx] = sum_e c_e(y) * sigmoid(xc_e(y) - gx)
//   c, xc depend only on (edge,row); sigmoid saturates outside |z| > TB:
//   - step part (gx < xc - TB): per-row difference array + block scan
//   - band part (<=32 cols, TB=15.5): edges bucketed into the 16 warp-owned
//     32-column windows; each warp gathers its bucket into registers.
//
// v3 changes vs v2 (20.8us, issue-bound):
//   * per-edge reciprocal 1/(dy+1e-8) precomputed once per block
//     -> per-(edge,row) test is FMA + 2 cmps, no division subroutine
//   * transcendental part of actives computed ONCE (c kept in registers);
//     fill phase re-derives only xc/gl/buckets (cheap)
//   * sigm(a)*sigm(b) = 1 / ((1+e^-a)(1+e^-b)) : 2 EX2 + 1 fast rcp
//   * bezier-point buffer aliased with band-record buffer (smem ~52KB,
//     4 CTAs/SM preserved; launch_bounds pins regs <= 32)

#define HH 512
#define WW 512
#define MM 2048           // 64 segments * 32 samples
#define TB 15.5f          // band half-width; tail err ~e^-15.5 ~ 1.8e-7
#define FLATCAP MM

__global__ void __launch_bounds__(512, 4)
k_render(const float* __restrict__ cp,
         const float* __restrict__ color,
         float* __restrict__ out)
{
    __shared__ float  scp[386];      // control points (193 x 2 interleaved)
    __shared__ float4 sE[MM];        // per-edge (y0, rdy, x0, dx); inert: y0=1e9
    __shared__ float  sD[WW];        // step difference array
    __shared__ float  spts[2 * MM];  // bezier pts (x|y); reused as flat float2[MM]
    __shared__ int    bcount[16], boff[16], bfill[16];
    __shared__ float  wsum[16];

    const int tid  = threadIdx.x;
    const int y    = blockIdx.x;
    const int lane = tid & 31;
    const int wid  = tid >> 5;

    if (tid < 386) scp[tid] = cp[tid];
    sD[tid] = 0.0f;
    if (tid < 16) { bcount[tid] = 0; bfill[tid] = 0; }
    __syncthreads();

    float* spx = spts;
    float* spy = spts + MM;

    // ---- cooperative bezier sampling (warp shares a segment: LDS broadcast) ----
    #pragma unroll
    for (int k = 0; k < 4; ++k) {
        int idx = tid + k * 512;
        int s = idx >> 5;            // segment 0..63
        int i = idx & 31;            // sample 0..31
        float t  = (float)i * (1.0f / 31.0f);   // linspace(0,1,32)
        float mt = 1.0f - t;
        float w0 = mt * mt * mt;
        float w1 = 3.0f * mt * mt * t;
        float w2 = 3.0f * mt * t * t;
        float w3 = t * t * t;
        const float* c0 = scp + 6 * s;
        spx[idx] = w0 * c0[0] + w1 * c0[2] + w2 * c0[4] + w3 * c0[6];
        spy[idx] = w0 * c0[1] + w1 * c0[3] + w2 * c0[5] + w3 * c0[7];
    }
    __syncthreads();

    // ---- per-edge precompute: reciprocal hoisted out of the row loop ----
    #pragma unroll
    for (int k = 0; k < 4; ++k) {
        int e = tid + k * 512, e1 = (e + 1) & (MM - 1);
        float y0 = spy[e], dy = spy[e1] - y0;
        float x0 = spx[e], dx = spx[e1] - x0;
        float rdy;
        if (fabsf(dy) < 1e-6f) { y0 = 1e9f; rdy = 1.0f; }   // masked -> t huge
        else rdy = __fdividef(1.0f, dy + 1e-8f);            // sign(rdy)=sign(dy)
        sE[e] = make_float4(y0, rdy, x0, dx);
    }
    __syncthreads();

    const float fy = (float)y;
    float cA[4];
    int   vmask = 0;
    float cstep = 0.0f;

    // ---- pass A: test edges, step scatter, bucket counts; keep c in regs ----
    #pragma unroll
    for (int k = 0; k < 4; ++k) {
        cA[k] = 0.0f;
        float4 E = sE[tid + k * 512];
        float t = (fy - E.x) * E.y;
        if (t < -1.2f || t > 2.2f) continue;     // c would be < ~4e-11
        // valid_t = sigm(20t)*sigm(20(1-t)) = 1/((1+e^-20t)(1+e^(20t-20)))
        float em = __expf(-20.0f * t);
        float ep = __expf(20.0f * t - 20.0f);
        float c  = __fdividef(1.0f, (1.0f + em) * (1.0f + ep));
        if (c < 1e-9f) continue;
        if (E.y < 0.0f) c = -c;                  // * sign(dy)
        float xc = fmaf(t, E.w, E.z);
        float gl = ceilf(xc - TB);
        if (gl > 0.0f) {                         // step: +c on [0, min(gl,512))
            cstep += c;
            if (gl < 512.0f) atomicAdd(&sD[(int)gl], -c);
        }
        if (gl + 31.0f >= 0.0f && gl < 512.0f) { // band reaches screen
            int igl = (int)gl;
            int b0 = (igl < 0 ? 0 : igl) >> 5;
            int hi = igl + 31; if (hi > 511) hi = 511;
            int b1 = hi >> 5;
            cA[k] = c;
            vmask |= 1 << k;
            atomicAdd(&bcount[b0], 1);
            if (b1 != b0) atomicAdd(&bcount[b1], 1);
        }
    }
    // single warp-reduction for the hot sD[0] address
    #pragma unroll
    for (int o = 16; o > 0; o >>= 1)
        cstep += __shfl_xor_sync(0xffffffffu, cstep, o);
    if (lane == 0 && cstep != 0.0f) atomicAdd(&sD[0], cstep);
    __syncthreads();

    // ---- exclusive prefix over 16 bucket counts ----
    if (wid == 0) {
        int v = (lane < 16) ? bcount[lane] : 0;
        int s = v;
        #pragma unroll
        for (int o = 1; o < 16; o <<= 1) {
            int n = __shfl_up_sync(0xffffffffu, s, o);
            if (lane >= o) s += n;
        }
        if (lane < 16) boff[lane] = s - v;
    }
    __syncthreads();

    // ---- fill: re-derive cheap geometry only (no transcendentals) ----
    float2* flat = reinterpret_cast<float2*>(spts);   // points are dead now
    #pragma unroll
    for (int k = 0; k < 4; ++k) {
        if (!(vmask & (1 << k))) continue;
        float4 E = sE[tid + k * 512];
        float t  = (fy - E.x) * E.y;
        float xc = fmaf(t, E.w, E.z);
        float gl = ceilf(xc - TB);
        int igl = (int)gl;
        int b0 = (igl < 0 ? 0 : igl) >> 5;
        int hi = igl + 31; if (hi > 511) hi = 511;
        int b1 = hi >> 5;
        float2 rec = make_float2(cA[k], xc);
        int p = atomicAdd(&bfill[b0], 1);
        int q = boff[b0] + p; if (q < FLATCAP) flat[q] = rec;
        if (b1 != b0) {
            p = atomicAdd(&bfill[b1], 1);
            q = boff[b1] + p; if (q < FLATCAP) flat[q] = rec;
        }
    }
    __syncthreads();

    // ---- band gather: warp w owns columns [32w, 32w+31]; registers only ----
    float acc = 0.0f;
    const float fgx = (float)tid;
    {
        int base = boff[wid];
        int lim  = base + bcount[wid];
        if (lim > FLATCAP) lim = FLATCAP;
        for (int i = base; i < lim; ++i) {
            float2 pr = flat[i];                 // LDS.64 broadcast
            float rel = fgx - ceilf(pr.y - TB);
            if (rel >= 0.0f && rel < 32.0f)      // sigm(xc-gx)
                acc += pr.x * __fdividef(1.0f, 1.0f + __expf(fgx - pr.y));
        }
    }

    // ---- inclusive scan of sD, combine, sigmoid, RGBA store ----
    float v = sD[tid];
    #pragma unroll
    for (int o = 1; o < 32; o <<= 1) {
        float n = __shfl_up_sync(0xffffffffu, v, o);
        if (lane >= o) v += n;
    }
    if (lane == 31) wsum[wid] = v;
    __syncthreads();
    if (wid == 0) {
        float w = (lane < 16) ? wsum[lane] : 0.0f;
        #pragma unroll
        for (int o = 1; o < 16; o <<= 1) {
            float n = __shfl_up_sync(0xffffffffu, w, o);
            if (lane >= o) w += n;
        }
        if (lane < 16) wsum[lane] = w;
    }
    __syncthreads();

    float prefix = (wid > 0) ? wsum[wid - 1] : 0.0f;
    float wind   = v + prefix + acc;
    float alpha  = __fdividef(1.0f, 1.0f + __expf(-4.0f * wind));

    float4 px = make_float4(color[0], color[1], color[2], alpha);
    reinterpret_cast<float4*>(out)[y * WW + tid] = px;
}

// ---------------------------------------------------------------------------
extern "C" void kernel_launch(void* const* d_in, const int* in_sizes, int n_in,
                              void* d_out, int out_size) {
    const float* cp    = (const float*)d_in[0];   // (193,2) f32
    const float* color = (const float*)d_in[1];   // (3,)   f32
    float* out = (float*)d_out;                   // (512,512,4) f32

    k_render<<<HH, 512>>>(cp, color, out);
}